// round 3
// baseline (speedup 1.0000x reference)
#include <cuda_runtime.h>

#define E_TOT   40000
#define N_NODES 4000
#define CCH     128
#define NCOEF   25
#define HID     64
#define FIN     128
#define F3      640

// ---------------- scratch (device globals; no allocs allowed) ----------------
__device__ __align__(16) float g_h[E_TOT * HID];            // 10.24 MB
__device__ __align__(16) float g_m0[(long long)E_TOT * F3]; // 102.4 MB
__device__ int   g_cnt[N_NODES];
__device__ int   g_off[N_NODES + 1];
__device__ int   g_cur[N_NODES];
__device__ int   g_list[E_TOT];

// ---------------- small helpers ----------------
__device__ __forceinline__ unsigned long long pack2(float x) {
    unsigned long long r;
    asm("mov.b64 %0, {%1, %1};" : "=l"(r) : "f"(x));
    return r;
}
__device__ __forceinline__ unsigned long long pack_pair(float lo, float hi) {
    unsigned long long r;
    asm("mov.b64 %0, {%1, %2};" : "=l"(r) : "f"(lo), "f"(hi));
    return r;
}
__device__ __forceinline__ void unpack2(unsigned long long v, float& lo, float& hi) {
    asm("mov.b64 {%0, %1}, %2;" : "=f"(lo), "=f"(hi) : "l"(v));
}
// packed dual-FMA: d = a*b + d (elementwise on f32x2)
__device__ __forceinline__ void fma2(unsigned long long& c, unsigned long long a,
                                     unsigned long long b) {
    asm("fma.rn.f32x2 %0, %1, %2, %0;" : "+l"(c) : "l"(a), "l"(b));
}
// all-reduce sum over 16-lane groups
__device__ __forceinline__ float allred16(float v) {
    v += __shfl_xor_sync(0xffffffffu, v, 8, 16);
    v += __shfl_xor_sync(0xffffffffu, v, 4, 16);
    v += __shfl_xor_sync(0xffffffffu, v, 2, 16);
    v += __shfl_xor_sync(0xffffffffu, v, 1, 16);
    return v;
}

// ---------------- edge-list building ----------------
__global__ void k_zero() {
    int i = blockIdx.x * blockDim.x + threadIdx.x;
    if (i < N_NODES) g_cnt[i] = 0;
}

__global__ void k_count(const int* __restrict__ ei, const int* __restrict__ noff) {
    int e = blockIdx.x * blockDim.x + threadIdx.x;
    if (e < E_TOT) {
        int d = ei[E_TOT + e] - noff[0];
        atomicAdd(&g_cnt[d], 1);
    }
}

__global__ void __launch_bounds__(1024) k_scan() {
    __shared__ int s[1024];
    const int tid = threadIdx.x;
    int v[4];
    int tot = 0;
#pragma unroll
    for (int j = 0; j < 4; j++) {
        int idx = tid * 4 + j;
        v[j] = (idx < N_NODES) ? g_cnt[idx] : 0;
        tot += v[j];
    }
    s[tid] = tot;
    __syncthreads();
    for (int off = 1; off < 1024; off <<= 1) {
        int t = (tid >= off) ? s[tid - off] : 0;
        __syncthreads();
        s[tid] += t;
        __syncthreads();
    }
    int run = s[tid] - tot;  // exclusive
#pragma unroll
    for (int j = 0; j < 4; j++) {
        int idx = tid * 4 + j;
        if (idx < N_NODES) {
            g_off[idx] = run;
            g_cur[idx] = run;
        }
        run += v[j];
    }
    if (tid == 1023) g_off[N_NODES] = s[1023];
}

__global__ void k_fill(const int* __restrict__ ei, const int* __restrict__ noff) {
    int e = blockIdx.x * blockDim.x + threadIdx.x;
    if (e < E_TOT) {
        int d = ei[E_TOT + e] - noff[0];
        int pos = atomicAdd(&g_cur[d], 1);
        g_list[pos] = e;
    }
}

// ---------------- K1: layers 1+2 (Linear->LN->SiLU) x2 ----------------
// CTA: 64 edges, 256 threads. thread = (eg 0..15 [4 edges], fg 0..15 [4 feats])
__global__ void __launch_bounds__(256) k_mlp12(
    const float* __restrict__ x_edge,
    const float* __restrict__ w1, const float* __restrict__ b1,
    const float* __restrict__ g1, const float* __restrict__ be1,
    const float* __restrict__ w2, const float* __restrict__ b2,
    const float* __restrict__ g2, const float* __restrict__ be2) {
    __shared__ __align__(16) float sbuf[64 * 132];  // reused: xe then h1 (stride 68)
    float* s_xe = sbuf;
    float* s_h1 = sbuf;

    const int tid = threadIdx.x;
    const int e0 = blockIdx.x * 64;

    {   // load x_edge tile [64][128] -> padded smem
        const float4* src = reinterpret_cast<const float4*>(x_edge + (long long)e0 * FIN);
#pragma unroll
        for (int i = tid; i < 64 * 32; i += 256) {
            int e = i >> 5, k4 = i & 31;
            float4 v = src[i];
            *reinterpret_cast<float4*>(&s_xe[e * 132 + k4 * 4]) = v;
        }
    }
    __syncthreads();

    const int fg = tid & 15;
    const int eg = tid >> 4;

    float b1a[4], g1a[4], be1a[4], b2a[4], g2a[4], be2a[4];
#pragma unroll
    for (int j = 0; j < 4; j++) {
        b1a[j]  = __ldg(b1 + fg * 4 + j);
        g1a[j]  = __ldg(g1 + fg * 4 + j);
        be1a[j] = __ldg(be1 + fg * 4 + j);
        b2a[j]  = __ldg(b2 + fg * 4 + j);
        g2a[j]  = __ldg(g2 + fg * 4 + j);
        be2a[j] = __ldg(be2 + fg * 4 + j);
    }

    // -------- layer 1 --------
    float acc[4][4] = {};
    for (int k = 0; k < 128; k++) {
        float4 b = __ldg(reinterpret_cast<const float4*>(w1 + k * 64 + fg * 4));
#pragma unroll
        for (int r = 0; r < 4; r++) {
            float a = s_xe[(eg * 4 + r) * 132 + k];
            acc[r][0] += a * b.x; acc[r][1] += a * b.y;
            acc[r][2] += a * b.z; acc[r][3] += a * b.w;
        }
    }
    float h1v[4][4];
#pragma unroll
    for (int r = 0; r < 4; r++) {
        float hv[4], s1 = 0.f;
#pragma unroll
        for (int j = 0; j < 4; j++) { hv[j] = acc[r][j] + b1a[j]; s1 += hv[j]; }
        s1 = allred16(s1);
        float mu = s1 * (1.f / 64.f);
        float s2 = 0.f;
#pragma unroll
        for (int j = 0; j < 4; j++) { float d = hv[j] - mu; s2 += d * d; }
        s2 = allred16(s2);
        float rstd = rsqrtf(s2 * (1.f / 64.f) + 1e-5f);
#pragma unroll
        for (int j = 0; j < 4; j++) {
            float y = (hv[j] - mu) * rstd * g1a[j] + be1a[j];
            h1v[r][j] = y / (1.f + __expf(-y));  // SiLU
        }
    }
    __syncthreads();  // all reads of s_xe done
#pragma unroll
    for (int r = 0; r < 4; r++)
#pragma unroll
        for (int j = 0; j < 4; j++) s_h1[(eg * 4 + r) * 68 + fg * 4 + j] = h1v[r][j];
    __syncthreads();

    // -------- layer 2 --------
    float acc2[4][4] = {};
    for (int k = 0; k < 64; k++) {
        float4 b = __ldg(reinterpret_cast<const float4*>(w2 + k * 64 + fg * 4));
#pragma unroll
        for (int r = 0; r < 4; r++) {
            float a = s_h1[(eg * 4 + r) * 68 + k];
            acc2[r][0] += a * b.x; acc2[r][1] += a * b.y;
            acc2[r][2] += a * b.z; acc2[r][3] += a * b.w;
        }
    }
#pragma unroll
    for (int r = 0; r < 4; r++) {
        float hv[4], s1 = 0.f;
#pragma unroll
        for (int j = 0; j < 4; j++) { hv[j] = acc2[r][j] + b2a[j]; s1 += hv[j]; }
        s1 = allred16(s1);
        float mu = s1 * (1.f / 64.f);
        float s2 = 0.f;
#pragma unroll
        for (int j = 0; j < 4; j++) { float d = hv[j] - mu; s2 += d * d; }
        s2 = allred16(s2);
        float rstd = rsqrtf(s2 * (1.f / 64.f) + 1e-5f);
        float4 o;
        float ov[4];
#pragma unroll
        for (int j = 0; j < 4; j++) {
            float y = (hv[j] - mu) * rstd * g2a[j] + be2a[j];
            ov[j] = y / (1.f + __expf(-y));
        }
        o.x = ov[0]; o.y = ov[1]; o.z = ov[2]; o.w = ov[3];
        *reinterpret_cast<float4*>(&g_h[(long long)(e0 + eg * 4 + r) * 64 + fg * 4]) = o;
    }
}

// ---------------- K2: layer 3 GEMM [64e][128f] per CTA, f32x2 packed ----------------
// grid (625, 5). 128 threads: eg = tid&7 (8 edges: eg+8r), fg = tid>>3 (8 feats).
__global__ void __launch_bounds__(128) k_mlp3(
    const float* __restrict__ w3, const float* __restrict__ b3,
    const float* __restrict__ edge_distance) {
    __shared__ __align__(16) float s_h[64 * 68];
    __shared__ __align__(16) float s_w[32 * 128];
    __shared__ __align__(16) float s_env[64];

    const int tid = threadIdx.x;
    const int e0 = blockIdx.x * 64;
    const int fc = blockIdx.y * 128;

    for (int i = tid; i < 64 * 16; i += 128) {
        int e = i >> 4, k4 = i & 15;
        float4 v = *reinterpret_cast<const float4*>(&g_h[(long long)(e0 + e) * 64 + k4 * 4]);
        *reinterpret_cast<float4*>(&s_h[e * 68 + k4 * 4]) = v;
    }
    if (tid < 64) {
        float d = edge_distance[e0 + tid] * (1.0f / 12.0f);
        float env = 0.f;
        if (d < 1.f) {
            float d2 = d * d, d4 = d2 * d2, d5 = d4 * d;
            env = 1.f + d5 * (-21.f + d * 35.f - d2 * 15.f);
        }
        s_env[tid] = env * 0.2f;  // env / RESCALE
    }

    const int eg = tid & 7;
    const int fg = tid >> 3;

    unsigned long long acc[8][4];
    {
        float4 blo = __ldg(reinterpret_cast<const float4*>(b3 + fc + fg * 8));
        float4 bhi = __ldg(reinterpret_cast<const float4*>(b3 + fc + fg * 8 + 4));
        unsigned long long bp[4];
        bp[0] = pack_pair(blo.x, blo.y); bp[1] = pack_pair(blo.z, blo.w);
        bp[2] = pack_pair(bhi.x, bhi.y); bp[3] = pack_pair(bhi.z, bhi.w);
#pragma unroll
        for (int r = 0; r < 8; r++)
#pragma unroll
            for (int j = 0; j < 4; j++) acc[r][j] = bp[j];
    }

#pragma unroll
    for (int kc = 0; kc < 2; kc++) {
        __syncthreads();
        for (int i = tid; i < 32 * 32; i += 128) {
            int k = i >> 5, f4 = i & 31;
            float4 v = __ldg(reinterpret_cast<const float4*>(
                w3 + (long long)(kc * 32 + k) * 640 + fc + f4 * 4));
            *reinterpret_cast<float4*>(&s_w[k * 128 + f4 * 4]) = v;
        }
        __syncthreads();
        for (int k = 0; k < 32; k++) {
            unsigned long long b2[4];
#pragma unroll
            for (int j = 0; j < 4; j++)
                b2[j] = *reinterpret_cast<const unsigned long long*>(
                    &s_w[k * 128 + fg * 8 + 2 * j]);
#pragma unroll
            for (int r = 0; r < 8; r++) {
                float a = s_h[(eg + 8 * r) * 68 + kc * 32 + k];
                unsigned long long a2 = pack2(a);
                fma2(acc[r][0], a2, b2[0]);
                fma2(acc[r][1], a2, b2[1]);
                fma2(acc[r][2], a2, b2[2]);
                fma2(acc[r][3], a2, b2[3]);
            }
        }
    }

#pragma unroll
    for (int r = 0; r < 8; r++) {
        int el = eg + 8 * r;
        float s = s_env[el];
        float o[8];
#pragma unroll
        for (int j = 0; j < 4; j++) {
            float lo, hi;
            unpack2(acc[r][j], lo, hi);
            o[2 * j] = lo * s;
            o[2 * j + 1] = hi * s;
        }
        long long base = (long long)(e0 + el) * 640 + fc + fg * 8;
        float4 v0, v1;
        v0.x = o[0]; v0.y = o[1]; v0.z = o[2]; v0.w = o[3];
        v1.x = o[4]; v1.y = o[5]; v1.z = o[6]; v1.w = o[7];
        *reinterpret_cast<float4*>(&g_m0[base]) = v0;
        *reinterpret_cast<float4*>(&g_m0[base + 4]) = v1;
    }
}

// ---------------- K3: per-node gather (atomic-free) ----------------
// out[n,i,c] = x[n,i,c] + sum_{e in edges(n)} sum_k wig[e,i,k(k+1)] * m0[e,k,c]
// CTA per node, 160 threads: iq = tid>>5 (5 rows each), cq = tid&31 (4 cols each)
__global__ void __launch_bounds__(160) k_gather(
    const float* __restrict__ x, const float* __restrict__ wig,
    float* __restrict__ out) {
    __shared__ __align__(16) float s_w[128];   // [k][i] (125 used)
    __shared__ __align__(16) float s_m0[640];  // [k][c]
    const int n = blockIdx.x;
    const int tid = threadIdx.x;
    const int iq = tid >> 5;
    const int cq = tid & 31;
    float acc[5][4] = {};
    const int beg = g_off[n], end = g_off[n + 1];
    for (int t = beg; t < end; t++) {
        const int e = g_list[t];
        __syncthreads();  // previous iteration's reads complete
        *reinterpret_cast<float4*>(&s_m0[tid * 4]) =
            *reinterpret_cast<const float4*>(&g_m0[(long long)e * 640 + tid * 4]);
        if (tid < 125) {
            int k = tid / 25;
            int i = tid - k * 25;
            int col = k * k + k;  // {0,2,6,12,20}
            s_w[k * 25 + i] = __ldg(&wig[(long long)e * 625 + i * 25 + col]);
        }
        __syncthreads();
#pragma unroll
        for (int k = 0; k < 5; k++) {
            float4 b = *reinterpret_cast<const float4*>(&s_m0[k * 128 + cq * 4]);
#pragma unroll
            for (int r = 0; r < 5; r++) {
                float a = s_w[k * 25 + iq * 5 + r];
                acc[r][0] += a * b.x; acc[r][1] += a * b.y;
                acc[r][2] += a * b.z; acc[r][3] += a * b.w;
            }
        }
    }
#pragma unroll
    for (int r = 0; r < 5; r++) {
        int i = iq * 5 + r;
        long long off = ((long long)n * 25 + i) * 128 + cq * 4;
        float4 xv = *reinterpret_cast<const float4*>(&x[off]);
        float4 o;
        o.x = xv.x + acc[r][0]; o.y = xv.y + acc[r][1];
        o.z = xv.z + acc[r][2]; o.w = xv.w + acc[r][3];
        *reinterpret_cast<float4*>(&out[off]) = o;
    }
}

// ---------------- launch ----------------
extern "C" void kernel_launch(void* const* d_in, const int* in_sizes, int n_in,
                              void* d_out, int out_size) {
    const float* x   = (const float*)d_in[0];
    const float* xe  = (const float*)d_in[1];
    const float* ed  = (const float*)d_in[2];
    const float* wig = (const float*)d_in[3];
    const int*   ei  = (const int*)d_in[4];
    const float* w1  = (const float*)d_in[5];
    const float* b1  = (const float*)d_in[6];
    const float* g1  = (const float*)d_in[7];
    const float* be1 = (const float*)d_in[8];
    const float* w2  = (const float*)d_in[9];
    const float* b2  = (const float*)d_in[10];
    const float* g2  = (const float*)d_in[11];
    const float* be2 = (const float*)d_in[12];
    const float* w3  = (const float*)d_in[13];
    const float* b3  = (const float*)d_in[14];
    const int* noff  = (const int*)d_in[15];
    float* out = (float*)d_out;

    k_zero<<<(N_NODES + 255) / 256, 256>>>();
    k_count<<<(E_TOT + 255) / 256, 256>>>(ei, noff);
    k_scan<<<1, 1024>>>();
    k_fill<<<(E_TOT + 255) / 256, 256>>>(ei, noff);
    k_mlp12<<<E_TOT / 64, 256>>>(xe, w1, b1, g1, be1, w2, b2, g2, be2);
    k_mlp3<<<dim3(E_TOT / 64, 5), 128>>>(w3, b3, ed);
    k_gather<<<N_NODES, 160>>>(x, wig, out);
    (void)in_sizes; (void)n_in; (void)out_size;
}